// round 5
// baseline (speedup 1.0000x reference)
#include <cuda_runtime.h>
#include <cuda_fp16.h>
#include <math.h>
#include <stdint.h>

// ===========================================================================
// DivFreeNetwork, forward-mode (primal + 4 tangents = 5 rows/point).
// GEMMs via mma.sync (HMMA) fp16 hi/lo split, 3 products, fp32 accumulate.
// R5: product-major MMA ordering, fragment double-buffering, 3-stage cp.async.
// ===========================================================================

#define DM 1024
#define ODIM 448
#define NLAY 4
#define MAXB 65536
#define MROWS (MAXB * 5)

__device__ __half g_Ah[(size_t)MROWS * DM];
__device__ __half g_Al[(size_t)MROWS * DM];
__device__ float  g_PRE[(size_t)MROWS * DM];
__device__ float  g_OUT[(size_t)MROWS * ODIM];
__device__ __half g_WThi[(size_t)NLAY * DM * DM + 512 * DM];
__device__ __half g_WTlo[(size_t)NLAY * DM * DM + 512 * DM];

// ------------------------------- helpers -----------------------------------
__device__ __forceinline__ uint32_t smem_u32(const void* p) {
    uint32_t a;
    asm("{ .reg .u64 t; cvta.to.shared.u64 t, %1; cvt.u32.u64 %0, t; }" : "=r"(a) : "l"(p));
    return a;
}
#define SWZ(o) ((o) ^ (((o) >> 3) & 0x70))

__device__ __forceinline__ void cp16(uint32_t so, const void* g) {
    asm volatile("cp.async.cg.shared.global [%0], [%1], 16;" :: "r"(so), "l"(g));
}
__device__ __forceinline__ void ldsm4(uint32_t* r, uint32_t addr) {
    asm volatile("ldmatrix.sync.aligned.m8n8.x4.shared.b16 {%0,%1,%2,%3}, [%4];"
                 : "=r"(r[0]), "=r"(r[1]), "=r"(r[2]), "=r"(r[3]) : "r"(addr));
}
__device__ __forceinline__ void mma16816(float* c, const uint32_t* a, uint32_t b0, uint32_t b1) {
    asm volatile("mma.sync.aligned.m16n8k16.row.col.f32.f16.f16.f32 "
                 "{%0,%1,%2,%3}, {%4,%5,%6,%7}, {%8,%9}, {%0,%1,%2,%3};"
                 : "+f"(c[0]), "+f"(c[1]), "+f"(c[2]), "+f"(c[3])
                 : "r"(a[0]), "r"(a[1]), "r"(a[2]), "r"(a[3]), "r"(b0), "r"(b1));
}

__device__ __forceinline__ float sigf(float p) { return 1.0f / (1.0f + expf(-p)); }

__device__ __forceinline__ void store4split(__half* ph, __half* pl, float4 v) {
    __align__(8) __half h[4], l[4];
    float vv[4] = {v.x, v.y, v.z, v.w};
#pragma unroll
    for (int i = 0; i < 4; i++) {
        h[i] = __float2half(vv[i]);
        l[i] = __float2half(vv[i] - __half2float(h[i]));
    }
    *(uint2*)ph = *(uint2*)h;
    *(uint2*)pl = *(uint2*)l;
}

// ------------------ prep: transpose + hi/lo split of weights ----------------
__global__ void prep_transpose(const float* __restrict__ W,
                               __half* __restrict__ Thi,
                               __half* __restrict__ Tlo,
                               int Krows, int Ncols)
{
    __shared__ float t[32][33];
    const float* Wz = W + (size_t)blockIdx.z * Krows * Ncols;
    __half* Hz = Thi + (size_t)blockIdx.z * Ncols * Krows;
    __half* Lz = Tlo + (size_t)blockIdx.z * Ncols * Krows;
    int n0 = blockIdx.x * 32, k0 = blockIdx.y * 32;
    int tx = threadIdx.x, ty = threadIdx.y;
#pragma unroll
    for (int i = 0; i < 4; i++)
        t[ty + 8 * i][tx] = Wz[(size_t)(k0 + ty + 8 * i) * Ncols + n0 + tx];
    __syncthreads();
#pragma unroll
    for (int i = 0; i < 4; i++) {
        int n = n0 + ty + 8 * i;
        float v = t[tx][ty + 8 * i];
        __half h = __float2half(v);
        Hz[(size_t)n * Krows + k0 + tx] = h;
        Lz[(size_t)n * Krows + k0 + tx] = __float2half(v - __half2float(h));
    }
}

// ---------------- layer 0: fused input GEMV + activation -------------------
__global__ void layer0_kernel(const float* __restrict__ x,
                              const float* __restrict__ W0,
                              const float* __restrict__ b0,
                              __half* __restrict__ Ah,
                              __half* __restrict__ Al, int B)
{
    int idx = blockIdx.x * blockDim.x + threadIdx.x;
    if (idx >= B * 256) return;
    int b = idx >> 8;
    int c = (idx & 255) * 4;
    float x0 = __ldg(x + b * 4 + 0), x1 = __ldg(x + b * 4 + 1);
    float x2 = __ldg(x + b * 4 + 2), x3 = __ldg(x + b * 4 + 3);
    float4 w0 = *(const float4*)(W0 + c);
    float4 w1 = *(const float4*)(W0 + 1024 + c);
    float4 w2 = *(const float4*)(W0 + 2048 + c);
    float4 w3 = *(const float4*)(W0 + 3072 + c);
    float4 bb = *(const float4*)(b0 + c);
    float p[4], act[4], d[4];
    float wv[4][4] = {{w0.x, w1.x, w2.x, w3.x}, {w0.y, w1.y, w2.y, w3.y},
                      {w0.z, w1.z, w2.z, w3.z}, {w0.w, w1.w, w2.w, w3.w}};
    float bv[4] = {bb.x, bb.y, bb.z, bb.w};
#pragma unroll
    for (int i = 0; i < 4; i++) {
        p[i] = fmaf(x0, wv[i][0], fmaf(x1, wv[i][1], fmaf(x2, wv[i][2], fmaf(x3, wv[i][3], bv[i]))));
        float sg = sigf(p[i]);
        act[i] = p[i] * sg;
        d[i] = sg * fmaf(p[i], 1.0f - sg, 1.0f);
    }
    size_t base = (size_t)b * (5 * DM) + c;
    store4split(Ah + base, Al + base, make_float4(act[0], act[1], act[2], act[3]));
#pragma unroll
    for (int j = 0; j < 4; j++) {
        float4 t = make_float4(d[0] * wv[0][j], d[1] * wv[1][j], d[2] * wv[2][j], d[3] * wv[3][j]);
        store4split(Ah + base + (j + 1) * DM, Al + base + (j + 1) * DM, t);
    }
}

// ---------------- activation: PRE fp32 -> ACT half hi/lo -------------------
__global__ void act_kernel(const float* __restrict__ PRE,
                           __half* __restrict__ Ah,
                           __half* __restrict__ Al, int B)
{
    int idx = blockIdx.x * blockDim.x + threadIdx.x;
    if (idx >= B * 256) return;
    int b = idx >> 8;
    int c = (idx & 255) * 4;
    size_t base = (size_t)b * (5 * DM) + c;
    float4 p = *(const float4*)(PRE + base);
    float pv[4] = {p.x, p.y, p.z, p.w}, av[4], dv[4];
#pragma unroll
    for (int i = 0; i < 4; i++) {
        float sg = sigf(pv[i]);
        av[i] = pv[i] * sg;
        dv[i] = sg * fmaf(pv[i], 1.0f - sg, 1.0f);
    }
    store4split(Ah + base, Al + base, make_float4(av[0], av[1], av[2], av[3]));
#pragma unroll
    for (int j = 1; j < 5; j++) {
        float4 t = *(const float4*)(PRE + base + j * DM);
        t.x *= dv[0]; t.y *= dv[1]; t.z *= dv[2]; t.w *= dv[3];
        store4split(Ah + base + j * DM, Al + base + j * DM, t);
    }
}

// ---------------- HMMA GEMM: C[M,N] = (Ahi+Alo) @ (Bhi+Blo)^T --------------
#define STG 65536               // 4 planes x 16KB per stage
#define NSTAGE 3

struct Frag {
    uint32_t ah[2][4], al[2][4];
    uint32_t bh[4][4], bl[4][4];
};

__device__ __forceinline__ void load_stage(uint32_t sb,
    const __half* Ah, const __half* Al, const __half* Bh, const __half* Bl,
    int row0, int col0, int k0, int K, int tid)
{
    const __half* gs[4] = {Ah, Al, Bh, Bl};
#pragma unroll
    for (int pl = 0; pl < 4; pl++) {
        const __half* g = gs[pl];
        int r0 = (pl < 2) ? row0 : col0;
        uint32_t pb = sb + pl * 16384;
#pragma unroll
        for (int it = 0; it < 4; it++) {
            int t = tid + it * 256;
            int r = t >> 3, cc = t & 7;
            cp16(pb + SWZ(r * 128 + cc * 16), g + (size_t)(r0 + r) * K + k0 + cc * 8);
        }
    }
    asm volatile("cp.async.commit_group;" ::: "memory");
}

__device__ __forceinline__ void load_frags(Frag& f, uint32_t stg,
                                           int wm, int wn, int lrow, int kadd, int ks)
{
    int col = ks * 16 + kadd;
    uint32_t Abh = stg, Abl = stg + 16384, Bbh = stg + 32768, Bbl = stg + 49152;
#pragma unroll
    for (int mi = 0; mi < 2; mi++) {
        uint32_t off = SWZ((wm * 32 + mi * 16 + lrow) * 128 + col * 2);
        ldsm4(f.ah[mi], Abh + off);
        ldsm4(f.al[mi], Abl + off);
    }
#pragma unroll
    for (int j = 0; j < 4; j++) {
        uint32_t off = SWZ((wn * 64 + j * 16 + lrow) * 128 + col * 2);
        ldsm4(f.bh[j], Bbh + off);
        ldsm4(f.bl[j], Bbl + off);
    }
}

__device__ __forceinline__ void compute_frag(float acc[2][8][4], const Frag& f)
{
    // product-major: all 16 accumulator chains visited before reuse
#pragma unroll
    for (int pr = 0; pr < 3; pr++) {
#pragma unroll
        for (int mi = 0; mi < 2; mi++) {
            const uint32_t* a = (pr == 2) ? f.al[mi] : f.ah[mi];
#pragma unroll
            for (int j = 0; j < 4; j++) {
                const uint32_t* b = (pr == 1) ? f.bl[j] : f.bh[j];
                mma16816(acc[mi][2 * j],     a, b[0], b[2]);
                mma16816(acc[mi][2 * j + 1], a, b[1], b[3]);
            }
        }
    }
}

__global__ void __launch_bounds__(256, 1)
gemm_mma(const __half* __restrict__ Ah, const __half* __restrict__ Al,
         const __half* __restrict__ Bh, const __half* __restrict__ Bl,
         const float* __restrict__ bias, float* __restrict__ C,
         int K, int ldc, int Nstore)
{
    extern __shared__ char smem[];
    uint32_t sbase = smem_u32(smem);
    int tid = threadIdx.x, wid = tid >> 5, lid = tid & 31;
    int wm = wid & 3, wn = wid >> 2;       // 4 warps along M, 2 along N
    int row0 = blockIdx.y * 128;
    int col0 = blockIdx.x * 128;

    float acc[2][8][4];
#pragma unroll
    for (int i = 0; i < 2; i++)
#pragma unroll
        for (int j = 0; j < 8; j++)
#pragma unroll
            for (int q = 0; q < 4; q++) acc[i][j][q] = 0.0f;

    const int KITER = K >> 6;
    load_stage(sbase + 0 * STG, Ah, Al, Bh, Bl, row0, col0, 0, K, tid);
    load_stage(sbase + 1 * STG, Ah, Al, Bh, Bl, row0, col0, 64, K, tid);
    load_stage(sbase + 2 * STG, Ah, Al, Bh, Bl, row0, col0, 128, K, tid);

    int lrow = lid & 15;
    int kadd = (lid & 16) ? 8 : 0;

    Frag f[2];
    for (int i = 0; i < KITER; i++) {
        asm volatile("cp.async.wait_group 2;" ::: "memory");
        __syncthreads();
        uint32_t stg = sbase + (i % NSTAGE) * STG;

        load_frags(f[0], stg, wm, wn, lrow, kadd, 0);
#pragma unroll
        for (int ks = 0; ks < 4; ks++) {
            if (ks < 3) load_frags(f[(ks + 1) & 1], stg, wm, wn, lrow, kadd, ks + 1);
            compute_frag(acc, f[ks & 1]);
        }
        __syncthreads();
        if (i + NSTAGE < KITER)
            load_stage(stg, Ah, Al, Bh, Bl, row0, col0, (i + NSTAGE) * 64, K, tid);
        else
            asm volatile("cp.async.commit_group;" ::: "memory");
    }

    // epilogue: C layout m16n8 — thread lid: rows lid/4 and lid/4+8, cols 2*(lid&3)
    int trow = lid >> 2, tcol = (lid & 3) * 2;
#pragma unroll
    for (int mi = 0; mi < 2; mi++) {
#pragma unroll
        for (int j = 0; j < 8; j++) {
            int gc = col0 + wn * 64 + j * 8 + tcol;
            if (gc >= Nstore) continue;
            int gr0 = row0 + wm * 32 + mi * 16 + trow;
            float2 v0 = make_float2(acc[mi][j][0], acc[mi][j][1]);
            float2 v1 = make_float2(acc[mi][j][2], acc[mi][j][3]);
            if (gr0 % 5 == 0)       { v0.x += bias[gc]; v0.y += bias[gc + 1]; }
            if ((gr0 + 8) % 5 == 0) { v1.x += bias[gc]; v1.y += bias[gc + 1]; }
            *(float2*)(C + (size_t)gr0 * ldc + gc) = v0;
            *(float2*)(C + (size_t)(gr0 + 8) * ldc + gc) = v1;
        }
    }
}

// ---------------- head: softmax-mixture derivative, warp per point ---------
__global__ void finalize_kernel(const float* __restrict__ OUT,
                                float* __restrict__ y, int B)
{
    int warp = (blockIdx.x * blockDim.x + threadIdx.x) >> 5;
    int lane = threadIdx.x & 31;
    if (warp >= B) return;
    const float* o = OUT + (size_t)warp * 5 * ODIM;

    float l0 = o[lane], l1 = o[lane + 32];
    float m = fmaxf(l0, l1);
#pragma unroll
    for (int s = 16; s; s >>= 1) m = fmaxf(m, __shfl_xor_sync(0xFFFFFFFFu, m, s));
    float e0 = expf(l0 - m), e1 = expf(l1 - m);
    float S = e0 + e1;
#pragma unroll
    for (int s = 16; s; s >>= 1) S += __shfl_xor_sync(0xFFFFFFFFu, S, s);
    float s0 = e0 / S, s1 = e1 / S;

    float v0[6], v1[6];
#pragma unroll
    for (int t = 0; t < 6; t++) {
        v0[t] = o[64 + 6 * lane + t];
        v1[t] = o[64 + 6 * (lane + 32) + t];
    }

    float Dm[4][6];
#pragma unroll
    for (int j = 0; j < 4; j++) {
        const float* tj = o + (size_t)(j + 1) * ODIM;
        float g0 = tj[lane], g1 = tj[lane + 32];
        float dot = s0 * g0 + s1 * g1;
#pragma unroll
        for (int s = 16; s; s >>= 1) dot += __shfl_xor_sync(0xFFFFFFFFu, dot, s);
#pragma unroll
        for (int t = 0; t < 6; t++) {
            float dv0 = tj[64 + 6 * lane + t];
            float dv1 = tj[64 + 6 * (lane + 32) + t];
            float val = s0 * fmaf(g0 - dot, v0[t], dv0) + s1 * fmaf(g1 - dot, v1[t], dv1);
#pragma unroll
            for (int s = 16; s; s >>= 1) val += __shfl_xor_sync(0xFFFFFFFFu, val, s);
            Dm[j][t] = val;
        }
    }
    if (lane == 0) {
        float u0 =  Dm[1][0] + Dm[2][1] + Dm[3][2];
        float u1 = -Dm[0][0] + Dm[2][3] + Dm[3][4];
        float u2 = -Dm[0][1] - Dm[1][3] + Dm[3][5];
        float u3 = -Dm[0][2] - Dm[1][4] - Dm[2][5];
        *(float4*)(y + (size_t)warp * 4) = make_float4(u0 * 10.0f, u1, u2, u3);
    }
}

// ---------------------------------------------------------------------------
extern "C" void kernel_launch(void* const* d_in, const int* in_sizes, int n_in,
                              void* d_out, int out_size)
{
    const float* x    = (const float*)d_in[0];
    const float* W0   = (const float*)d_in[1];
    const float* b0   = (const float*)d_in[2];
    const float* Wh   = (const float*)d_in[3];
    const float* bh   = (const float*)d_in[4];
    const float* Wout = (const float*)d_in[5];
    const float* bout = (const float*)d_in[6];
    float* y = (float*)d_out;

    int B = in_sizes[0] / 4;
    int M = B * 5;

    __half *Ah, *Al, *WThi, *WTlo;
    float *PRE, *OUTB;
    cudaGetSymbolAddress((void**)&Ah, g_Ah);
    cudaGetSymbolAddress((void**)&Al, g_Al);
    cudaGetSymbolAddress((void**)&PRE, g_PRE);
    cudaGetSymbolAddress((void**)&OUTB, g_OUT);
    cudaGetSymbolAddress((void**)&WThi, g_WThi);
    cudaGetSymbolAddress((void**)&WTlo, g_WTlo);

    static int smem_set = 0;
    if (!smem_set) {
        cudaFuncSetAttribute(gemm_mma, cudaFuncAttributeMaxDynamicSharedMemorySize,
                             NSTAGE * STG);
        smem_set = 1;
    }

    prep_transpose<<<dim3(32, 32, NLAY), dim3(32, 8)>>>(Wh, WThi, WTlo, DM, DM);
    prep_transpose<<<dim3(ODIM / 32, 32, 1), dim3(32, 8)>>>(
        Wout, WThi + (size_t)NLAY * DM * DM, WTlo + (size_t)NLAY * DM * DM, DM, ODIM);

    layer0_kernel<<<(B * 256 + 255) / 256, 256>>>(x, W0, b0, Ah, Al, B);

    dim3 gH(DM / 128, M / 128);
    for (int l = 0; l < NLAY; l++) {
        gemm_mma<<<gH, 256, NSTAGE * STG>>>(Ah, Al,
            WThi + (size_t)l * DM * DM, WTlo + (size_t)l * DM * DM,
            bh + (size_t)l * DM, PRE, DM, DM, DM);
        act_kernel<<<(B * 256 + 255) / 256, 256>>>(PRE, Ah, Al, B);
    }

    dim3 gO(4, M / 128);
    gemm_mma<<<gO, 256, NSTAGE * STG>>>(Ah, Al,
        WThi + (size_t)NLAY * DM * DM, WTlo + (size_t)NLAY * DM * DM,
        bout, OUTB, DM, ODIM, ODIM);

    finalize_kernel<<<(B * 32 + 255) / 256, 256>>>(OUTB, y, B);
}

// round 6
// speedup vs baseline: 1.7005x; 1.7005x over previous
#include <cuda_runtime.h>
#include <cuda_fp16.h>
#include <math.h>
#include <stdint.h>

// ===========================================================================
// DivFreeNetwork, forward-mode (primal + 4 tangents = 5 rows/point).
// GEMMs via mma.sync (HMMA) fp16 hi/lo split, 3 products, fp32 accumulate.
// R6: 128x64 CTA tile, 2 CTAs/SM co-residency, product-major MMA order,
//     single-buffered fragments (R5 regression reverted).
// ===========================================================================

#define DM 1024
#define ODIM 448
#define NLAY 4
#define MAXB 65536
#define MROWS (MAXB * 5)

__device__ __half g_Ah[(size_t)MROWS * DM];
__device__ __half g_Al[(size_t)MROWS * DM];
__device__ float  g_PRE[(size_t)MROWS * DM];
__device__ float  g_OUT[(size_t)MROWS * ODIM];
__device__ __half g_WThi[(size_t)NLAY * DM * DM + 512 * DM];
__device__ __half g_WTlo[(size_t)NLAY * DM * DM + 512 * DM];

// ------------------------------- helpers -----------------------------------
__device__ __forceinline__ uint32_t smem_u32(const void* p) {
    uint32_t a;
    asm("{ .reg .u64 t; cvta.to.shared.u64 t, %1; cvt.u32.u64 %0, t; }" : "=r"(a) : "l"(p));
    return a;
}
#define SWZ(o) ((o) ^ (((o) >> 3) & 0x70))

__device__ __forceinline__ void cp16(uint32_t so, const void* g) {
    asm volatile("cp.async.cg.shared.global [%0], [%1], 16;" :: "r"(so), "l"(g));
}
__device__ __forceinline__ void ldsm4(uint32_t* r, uint32_t addr) {
    asm volatile("ldmatrix.sync.aligned.m8n8.x4.shared.b16 {%0,%1,%2,%3}, [%4];"
                 : "=r"(r[0]), "=r"(r[1]), "=r"(r[2]), "=r"(r[3]) : "r"(addr));
}
__device__ __forceinline__ void mma16816(float* c, const uint32_t* a, uint32_t b0, uint32_t b1) {
    asm volatile("mma.sync.aligned.m16n8k16.row.col.f32.f16.f16.f32 "
                 "{%0,%1,%2,%3}, {%4,%5,%6,%7}, {%8,%9}, {%0,%1,%2,%3};"
                 : "+f"(c[0]), "+f"(c[1]), "+f"(c[2]), "+f"(c[3])
                 : "r"(a[0]), "r"(a[1]), "r"(a[2]), "r"(a[3]), "r"(b0), "r"(b1));
}

__device__ __forceinline__ float sigf(float p) { return 1.0f / (1.0f + expf(-p)); }

__device__ __forceinline__ void store4split(__half* ph, __half* pl, float4 v) {
    __align__(8) __half h[4], l[4];
    float vv[4] = {v.x, v.y, v.z, v.w};
#pragma unroll
    for (int i = 0; i < 4; i++) {
        h[i] = __float2half(vv[i]);
        l[i] = __float2half(vv[i] - __half2float(h[i]));
    }
    *(uint2*)ph = *(uint2*)h;
    *(uint2*)pl = *(uint2*)l;
}

// ------------------ prep: transpose + hi/lo split of weights ----------------
__global__ void prep_transpose(const float* __restrict__ W,
                               __half* __restrict__ Thi,
                               __half* __restrict__ Tlo,
                               int Krows, int Ncols)
{
    __shared__ float t[32][33];
    const float* Wz = W + (size_t)blockIdx.z * Krows * Ncols;
    __half* Hz = Thi + (size_t)blockIdx.z * Ncols * Krows;
    __half* Lz = Tlo + (size_t)blockIdx.z * Ncols * Krows;
    int n0 = blockIdx.x * 32, k0 = blockIdx.y * 32;
    int tx = threadIdx.x, ty = threadIdx.y;
#pragma unroll
    for (int i = 0; i < 4; i++)
        t[ty + 8 * i][tx] = Wz[(size_t)(k0 + ty + 8 * i) * Ncols + n0 + tx];
    __syncthreads();
#pragma unroll
    for (int i = 0; i < 4; i++) {
        int n = n0 + ty + 8 * i;
        float v = t[tx][ty + 8 * i];
        __half h = __float2half(v);
        Hz[(size_t)n * Krows + k0 + tx] = h;
        Lz[(size_t)n * Krows + k0 + tx] = __float2half(v - __half2float(h));
    }
}

// ---------------- layer 0: fused input GEMV + activation -------------------
__global__ void layer0_kernel(const float* __restrict__ x,
                              const float* __restrict__ W0,
                              const float* __restrict__ b0,
                              __half* __restrict__ Ah,
                              __half* __restrict__ Al, int B)
{
    int idx = blockIdx.x * blockDim.x + threadIdx.x;
    if (idx >= B * 256) return;
    int b = idx >> 8;
    int c = (idx & 255) * 4;
    float x0 = __ldg(x + b * 4 + 0), x1 = __ldg(x + b * 4 + 1);
    float x2 = __ldg(x + b * 4 + 2), x3 = __ldg(x + b * 4 + 3);
    float4 w0 = *(const float4*)(W0 + c);
    float4 w1 = *(const float4*)(W0 + 1024 + c);
    float4 w2 = *(const float4*)(W0 + 2048 + c);
    float4 w3 = *(const float4*)(W0 + 3072 + c);
    float4 bb = *(const float4*)(b0 + c);
    float p[4], act[4], d[4];
    float wv[4][4] = {{w0.x, w1.x, w2.x, w3.x}, {w0.y, w1.y, w2.y, w3.y},
                      {w0.z, w1.z, w2.z, w3.z}, {w0.w, w1.w, w2.w, w3.w}};
    float bv[4] = {bb.x, bb.y, bb.z, bb.w};
#pragma unroll
    for (int i = 0; i < 4; i++) {
        p[i] = fmaf(x0, wv[i][0], fmaf(x1, wv[i][1], fmaf(x2, wv[i][2], fmaf(x3, wv[i][3], bv[i]))));
        float sg = sigf(p[i]);
        act[i] = p[i] * sg;
        d[i] = sg * fmaf(p[i], 1.0f - sg, 1.0f);
    }
    size_t base = (size_t)b * (5 * DM) + c;
    store4split(Ah + base, Al + base, make_float4(act[0], act[1], act[2], act[3]));
#pragma unroll
    for (int j = 0; j < 4; j++) {
        float4 t = make_float4(d[0] * wv[0][j], d[1] * wv[1][j], d[2] * wv[2][j], d[3] * wv[3][j]);
        store4split(Ah + base + (j + 1) * DM, Al + base + (j + 1) * DM, t);
    }
}

// ---------------- activation: PRE fp32 -> ACT half hi/lo -------------------
__global__ void act_kernel(const float* __restrict__ PRE,
                           __half* __restrict__ Ah,
                           __half* __restrict__ Al, int B)
{
    int idx = blockIdx.x * blockDim.x + threadIdx.x;
    if (idx >= B * 256) return;
    int b = idx >> 8;
    int c = (idx & 255) * 4;
    size_t base = (size_t)b * (5 * DM) + c;
    float4 p = *(const float4*)(PRE + base);
    float pv[4] = {p.x, p.y, p.z, p.w}, av[4], dv[4];
#pragma unroll
    for (int i = 0; i < 4; i++) {
        float sg = sigf(pv[i]);
        av[i] = pv[i] * sg;
        dv[i] = sg * fmaf(pv[i], 1.0f - sg, 1.0f);
    }
    store4split(Ah + base, Al + base, make_float4(av[0], av[1], av[2], av[3]));
#pragma unroll
    for (int j = 1; j < 5; j++) {
        float4 t = *(const float4*)(PRE + base + j * DM);
        t.x *= dv[0]; t.y *= dv[1]; t.z *= dv[2]; t.w *= dv[3];
        store4split(Ah + base + j * DM, Al + base + j * DM, t);
    }
}

// ---------------- HMMA GEMM: C[M,N] = (Ahi+Alo) @ (Bhi+Blo)^T --------------
// CTA tile 128(M) x 64(N), BK=64. smem/stage: Ahi 16K, Alo 16K, Bhi 8K, Blo 8K.
#define STG 49152
#define NSTAGE 2

__device__ __forceinline__ void load_stage(uint32_t sb,
    const __half* Ah, const __half* Al, const __half* Bh, const __half* Bl,
    int row0, int col0, int k0, int K, int tid)
{
    const __half* gs[4] = {Ah, Al, Bh, Bl};
    const uint32_t po[4] = {0u, 16384u, 32768u, 40960u};
#pragma unroll
    for (int pl = 0; pl < 4; pl++) {
        const __half* g = gs[pl];
        int r0 = (pl < 2) ? row0 : col0;
        int iters = (pl < 2) ? 4 : 2;            // 128 rows vs 64 rows, 8 cp16/row
        uint32_t pb = sb + po[pl];
#pragma unroll
        for (int it = 0; it < 4; it++) {
            if (it >= iters) break;
            int t = tid + it * 256;
            int r = t >> 3, cc = t & 7;
            cp16(pb + SWZ(r * 128 + cc * 16), g + (size_t)(r0 + r) * K + k0 + cc * 8);
        }
    }
    asm volatile("cp.async.commit_group;" ::: "memory");
}

__global__ void __launch_bounds__(256, 2)
gemm_mma(const __half* __restrict__ Ah, const __half* __restrict__ Al,
         const __half* __restrict__ Bh, const __half* __restrict__ Bl,
         const float* __restrict__ bias, float* __restrict__ C,
         int K, int ldc, int Nstore)
{
    extern __shared__ char smem[];
    uint32_t sbase = smem_u32(smem);
    int tid = threadIdx.x, wid = tid >> 5, lid = tid & 31;
    int wm = wid & 3, wn = wid >> 2;       // 4 warps along M (32 rows), 2 along N (32 cols)
    int row0 = blockIdx.y * 128;
    int col0 = blockIdx.x * 64;

    float acc[2][4][4];
#pragma unroll
    for (int i = 0; i < 2; i++)
#pragma unroll
        for (int j = 0; j < 4; j++)
#pragma unroll
            for (int q = 0; q < 4; q++) acc[i][j][q] = 0.0f;

    const int KITER = K >> 6;
    load_stage(sbase + 0 * STG, Ah, Al, Bh, Bl, row0, col0, 0, K, tid);
    load_stage(sbase + 1 * STG, Ah, Al, Bh, Bl, row0, col0, 64, K, tid);

    int lrow = lid & 15;
    int kadd = (lid & 16) ? 8 : 0;

    for (int i = 0; i < KITER; i++) {
        asm volatile("cp.async.wait_group 1;" ::: "memory");
        __syncthreads();
        uint32_t stg = sbase + (i & 1) * STG;
        uint32_t Abh = stg, Abl = stg + 16384, Bbh = stg + 32768, Bbl = stg + 40960;

#pragma unroll
        for (int ks = 0; ks < 4; ks++) {
            int col = ks * 16 + kadd;
            uint32_t ahi[2][4], alo[2][4], bhi[2][4], blo[2][4];
#pragma unroll
            for (int mi = 0; mi < 2; mi++) {
                uint32_t off = SWZ((wm * 32 + mi * 16 + lrow) * 128 + col * 2);
                ldsm4(ahi[mi], Abh + off);
                ldsm4(alo[mi], Abl + off);
            }
#pragma unroll
            for (int j = 0; j < 2; j++) {
                uint32_t off = SWZ((wn * 32 + j * 16 + lrow) * 128 + col * 2);
                ldsm4(bhi[j], Bbh + off);
                ldsm4(blo[j], Bbl + off);
            }
            // product-major: 8 MMAs per product, same-acc reuse distance = 8
#pragma unroll
            for (int mi = 0; mi < 2; mi++)
#pragma unroll
                for (int j = 0; j < 2; j++) {
                    mma16816(acc[mi][2 * j],     ahi[mi], bhi[j][0], bhi[j][2]);
                    mma16816(acc[mi][2 * j + 1], ahi[mi], bhi[j][1], bhi[j][3]);
                }
#pragma unroll
            for (int mi = 0; mi < 2; mi++)
#pragma unroll
                for (int j = 0; j < 2; j++) {
                    mma16816(acc[mi][2 * j],     ahi[mi], blo[j][0], blo[j][2]);
                    mma16816(acc[mi][2 * j + 1], ahi[mi], blo[j][1], blo[j][3]);
                }
#pragma unroll
            for (int mi = 0; mi < 2; mi++)
#pragma unroll
                for (int j = 0; j < 2; j++) {
                    mma16816(acc[mi][2 * j],     alo[mi], bhi[j][0], bhi[j][2]);
                    mma16816(acc[mi][2 * j + 1], alo[mi], bhi[j][1], bhi[j][3]);
                }
        }
        __syncthreads();
        if (i + NSTAGE < KITER)
            load_stage(stg, Ah, Al, Bh, Bl, row0, col0, (i + NSTAGE) * 64, K, tid);
        else
            asm volatile("cp.async.commit_group;" ::: "memory");
    }

    // epilogue: m16n8 frag — thread lid: rows lid/4, lid/4+8; cols 2*(lid&3)
    int trow = lid >> 2, tcol = (lid & 3) * 2;
#pragma unroll
    for (int mi = 0; mi < 2; mi++) {
#pragma unroll
        for (int j = 0; j < 4; j++) {
            int gc = col0 + wn * 32 + j * 8 + tcol;
            if (gc >= Nstore) continue;
            int gr0 = row0 + wm * 32 + mi * 16 + trow;
            float2 v0 = make_float2(acc[mi][j][0], acc[mi][j][1]);
            float2 v1 = make_float2(acc[mi][j][2], acc[mi][j][3]);
            if (gr0 % 5 == 0)       { v0.x += bias[gc]; v0.y += bias[gc + 1]; }
            if ((gr0 + 8) % 5 == 0) { v1.x += bias[gc]; v1.y += bias[gc + 1]; }
            *(float2*)(C + (size_t)gr0 * ldc + gc) = v0;
            *(float2*)(C + (size_t)(gr0 + 8) * ldc + gc) = v1;
        }
    }
}

// ---------------- head: softmax-mixture derivative, warp per point ---------
__global__ void finalize_kernel(const float* __restrict__ OUT,
                                float* __restrict__ y, int B)
{
    int warp = (blockIdx.x * blockDim.x + threadIdx.x) >> 5;
    int lane = threadIdx.x & 31;
    if (warp >= B) return;
    const float* o = OUT + (size_t)warp * 5 * ODIM;

    float l0 = o[lane], l1 = o[lane + 32];
    float m = fmaxf(l0, l1);
#pragma unroll
    for (int s = 16; s; s >>= 1) m = fmaxf(m, __shfl_xor_sync(0xFFFFFFFFu, m, s));
    float e0 = expf(l0 - m), e1 = expf(l1 - m);
    float S = e0 + e1;
#pragma unroll
    for (int s = 16; s; s >>= 1) S += __shfl_xor_sync(0xFFFFFFFFu, S, s);
    float s0 = e0 / S, s1 = e1 / S;

    float v0[6], v1[6];
#pragma unroll
    for (int t = 0; t < 6; t++) {
        v0[t] = o[64 + 6 * lane + t];
        v1[t] = o[64 + 6 * (lane + 32) + t];
    }

    float Dm[4][6];
#pragma unroll
    for (int j = 0; j < 4; j++) {
        const float* tj = o + (size_t)(j + 1) * ODIM;
        float g0 = tj[lane], g1 = tj[lane + 32];
        float dot = s0 * g0 + s1 * g1;
#pragma unroll
        for (int s = 16; s; s >>= 1) dot += __shfl_xor_sync(0xFFFFFFFFu, dot, s);
#pragma unroll
        for (int t = 0; t < 6; t++) {
            float dv0 = tj[64 + 6 * lane + t];
            float dv1 = tj[64 + 6 * (lane + 32) + t];
            float val = s0 * fmaf(g0 - dot, v0[t], dv0) + s1 * fmaf(g1 - dot, v1[t], dv1);
#pragma unroll
            for (int s = 16; s; s >>= 1) val += __shfl_xor_sync(0xFFFFFFFFu, val, s);
            Dm[j][t] = val;
        }
    }
    if (lane == 0) {
        float u0 =  Dm[1][0] + Dm[2][1] + Dm[3][2];
        float u1 = -Dm[0][0] + Dm[2][3] + Dm[3][4];
        float u2 = -Dm[0][1] - Dm[1][3] + Dm[3][5];
        float u3 = -Dm[0][2] - Dm[1][4] - Dm[2][5];
        *(float4*)(y + (size_t)warp * 4) = make_float4(u0 * 10.0f, u1, u2, u3);
    }
}

// ---------------------------------------------------------------------------
extern "C" void kernel_launch(void* const* d_in, const int* in_sizes, int n_in,
                              void* d_out, int out_size)
{
    const float* x    = (const float*)d_in[0];
    const float* W0   = (const float*)d_in[1];
    const float* b0   = (const float*)d_in[2];
    const float* Wh   = (const float*)d_in[3];
    const float* bh   = (const float*)d_in[4];
    const float* Wout = (const float*)d_in[5];
    const float* bout = (const float*)d_in[6];
    float* y = (float*)d_out;

    int B = in_sizes[0] / 4;
    int M = B * 5;

    __half *Ah, *Al, *WThi, *WTlo;
    float *PRE, *OUTB;
    cudaGetSymbolAddress((void**)&Ah, g_Ah);
    cudaGetSymbolAddress((void**)&Al, g_Al);
    cudaGetSymbolAddress((void**)&PRE, g_PRE);
    cudaGetSymbolAddress((void**)&OUTB, g_OUT);
    cudaGetSymbolAddress((void**)&WThi, g_WThi);
    cudaGetSymbolAddress((void**)&WTlo, g_WTlo);

    static int smem_set = 0;
    if (!smem_set) {
        cudaFuncSetAttribute(gemm_mma, cudaFuncAttributeMaxDynamicSharedMemorySize,
                             NSTAGE * STG);
        smem_set = 1;
    }

    prep_transpose<<<dim3(32, 32, NLAY), dim3(32, 8)>>>(Wh, WThi, WTlo, DM, DM);
    prep_transpose<<<dim3(ODIM / 32, 32, 1), dim3(32, 8)>>>(
        Wout, WThi + (size_t)NLAY * DM * DM, WTlo + (size_t)NLAY * DM * DM, DM, ODIM);

    layer0_kernel<<<(B * 256 + 255) / 256, 256>>>(x, W0, b0, Ah, Al, B);

    dim3 gH(DM / 64, M / 128);
    for (int l = 0; l < NLAY; l++) {
        gemm_mma<<<gH, 256, NSTAGE * STG>>>(Ah, Al,
            WThi + (size_t)l * DM * DM, WTlo + (size_t)l * DM * DM,
            bh + (size_t)l * DM, PRE, DM, DM, DM);
        act_kernel<<<(B * 256 + 255) / 256, 256>>>(PRE, Ah, Al, B);
    }

    dim3 gO(512 / 64, M / 128);
    gemm_mma<<<gO, 256, NSTAGE * STG>>>(Ah, Al,
        WThi + (size_t)NLAY * DM * DM, WTlo + (size_t)NLAY * DM * DM,
        bout, OUTB, DM, ODIM, ODIM);

    finalize_kernel<<<(B * 32 + 255) / 256, 256>>>(OUTB, y, B);
}